// round 2
// baseline (speedup 1.0000x reference)
#include <cuda_runtime.h>

// LSTMPolicy fused kernel, round 0 baseline.
// Exploits: zero initial state => Whh* unused, f-gate unused (c = sigm(i)*tanh(g)).
// Per row: L0 384x64 MAC, L1 384x128 MAC, heads 17x128 MAC.
// One thread per batch row, 256 threads/block, weights staged via smem broadcast.

#define BATCH   65536
#define HIDDEN  128
#define INPUT   64
#define NACT    16
#define TPB     256

#define HB_STRIDE 132              // 128 + 4 pad: conflict-free LDS.128 per 8-lane phase
#define STAGE_K   8                // gate-triples (k indices) per stage
#define STAGE_ROWS (3 * STAGE_K)   // 24 weight rows per stage (i,g,o)

__device__ __forceinline__ float sigm(float v) {
    return __fdividef(1.0f, 1.0f + __expf(-v));
}
__device__ __forceinline__ float tanh_fast(float v) {
    // tanh(x) = 2*sigmoid(2x) - 1 ; saturates correctly for large |x|
    return fmaf(2.0f, sigm(2.0f * v), -1.0f);
}

__global__ __launch_bounds__(TPB)
void lstm_policy_fused(const float* __restrict__ x,
                       const float* __restrict__ Wih0,
                       const float* __restrict__ bih0,
                       const float* __restrict__ bhh0,
                       const float* __restrict__ Wih1,
                       const float* __restrict__ bih1,
                       const float* __restrict__ bhh1,
                       const float* __restrict__ Wp,
                       const float* __restrict__ bp,
                       const float* __restrict__ Wv,
                       const float* __restrict__ bv,
                       float* __restrict__ out)
{
    extern __shared__ float sm[];
    float* hbuf = sm;                                  // [TPB][HB_STRIDE]
    float* wst  = sm + TPB * HB_STRIDE;                // [24][128] weight stage
    float* hw   = wst + STAGE_ROWS * HIDDEN;           // [17][128] head weights

    const int t   = threadIdx.x;
    const int row = blockIdx.x * TPB + t;

    // ---- stage head weights (Wp rows 0..15, Wv row 16) ----
    for (int i = t; i < 17 * HIDDEN; i += TPB) {
        hw[i] = (i < NACT * HIDDEN) ? Wp[i] : Wv[i - NACT * HIDDEN];
    }
    // (first consumer is in the L1 loop; many __syncthreads before that)

    // ---- x row into registers ----
    float xr[INPUT];
    {
        const float4* xg = reinterpret_cast<const float4*>(x + (size_t)row * INPUT);
        #pragma unroll
        for (int j = 0; j < INPUT / 4; j++) {
            float4 v = __ldg(xg + j);
            xr[4 * j + 0] = v.x; xr[4 * j + 1] = v.y;
            xr[4 * j + 2] = v.z; xr[4 * j + 3] = v.w;
        }
    }

    // =======================  Layer 0  =======================
    // gates: i = rows [0,128), g = rows [256,384), o = rows [384,512) of Wih0
    for (int s = 0; s < HIDDEN / STAGE_K; s++) {
        const int k0 = s * STAGE_K;
        __syncthreads();                 // protect wst from previous stage readers
        for (int idx = t; idx < STAGE_ROWS * INPUT; idx += TPB) {
            int r = idx / INPUT, c = idx - r * INPUT;
            int gate = r >> 3;           // 0:i 1:g 2:o
            int kk = k0 + (r & 7);
            int grow = (gate == 0) ? kk : (gate == 1) ? (2 * HIDDEN + kk) : (3 * HIDDEN + kk);
            wst[r * INPUT + c] = Wih0[grow * INPUT + c];
        }
        __syncthreads();

        float acc[STAGE_ROWS];
        #pragma unroll
        for (int r = 0; r < STAGE_ROWS; r++) acc[r] = 0.0f;

        #pragma unroll
        for (int j4 = 0; j4 < INPUT / 4; j4++) {
            const float a0 = xr[4 * j4 + 0], a1 = xr[4 * j4 + 1];
            const float a2 = xr[4 * j4 + 2], a3 = xr[4 * j4 + 3];
            #pragma unroll
            for (int r = 0; r < STAGE_ROWS; r++) {
                float4 w = reinterpret_cast<const float4*>(wst + r * INPUT)[j4]; // broadcast
                acc[r] = fmaf(w.x, a0, acc[r]);
                acc[r] = fmaf(w.y, a1, acc[r]);
                acc[r] = fmaf(w.z, a2, acc[r]);
                acc[r] = fmaf(w.w, a3, acc[r]);
            }
        }

        #pragma unroll
        for (int r = 0; r < STAGE_K; r++) {
            const int k = k0 + r;
            float iv = acc[r]              + bih0[k]              + bhh0[k];
            float gv = acc[STAGE_K + r]    + bih0[2 * HIDDEN + k] + bhh0[2 * HIDDEN + k];
            float ov = acc[2 * STAGE_K + r]+ bih0[3 * HIDDEN + k] + bhh0[3 * HIDDEN + k];
            float c  = sigm(iv) * tanh_fast(gv);     // c_prev = 0 => f-gate dead
            float h  = sigm(ov) * tanh_fast(c);
            hbuf[t * HB_STRIDE + k] = h;             // own row only, no cross-thread hazard
        }
    }

    // =======================  Layer 1 + fused heads  =======================
    float pv[NACT + 1];
    #pragma unroll
    for (int a = 0; a < NACT; a++) pv[a] = bp[a];
    pv[NACT] = bv[0];

    for (int s = 0; s < HIDDEN / STAGE_K; s++) {
        const int k0 = s * STAGE_K;
        __syncthreads();
        for (int idx = t; idx < STAGE_ROWS * HIDDEN; idx += TPB) {
            int r = idx / HIDDEN, c = idx - r * HIDDEN;
            int gate = r >> 3;
            int kk = k0 + (r & 7);
            int grow = (gate == 0) ? kk : (gate == 1) ? (2 * HIDDEN + kk) : (3 * HIDDEN + kk);
            wst[r * HIDDEN + c] = Wih1[grow * HIDDEN + c];
        }
        __syncthreads();

        float acc[STAGE_ROWS];
        #pragma unroll
        for (int r = 0; r < STAGE_ROWS; r++) acc[r] = 0.0f;

        const float4* hrow = reinterpret_cast<const float4*>(hbuf + t * HB_STRIDE);
        #pragma unroll
        for (int j4 = 0; j4 < HIDDEN / 4; j4++) {
            float4 hv = hrow[j4];                    // conflict-free (stride 132)
            #pragma unroll
            for (int r = 0; r < STAGE_ROWS; r++) {
                float4 w = reinterpret_cast<const float4*>(wst + r * HIDDEN)[j4]; // broadcast
                acc[r] = fmaf(w.x, hv.x, acc[r]);
                acc[r] = fmaf(w.y, hv.y, acc[r]);
                acc[r] = fmaf(w.z, hv.z, acc[r]);
                acc[r] = fmaf(w.w, hv.w, acc[r]);
            }
        }

        #pragma unroll
        for (int r = 0; r < STAGE_K; r++) {
            const int k = k0 + r;
            float iv = acc[r]               + bih1[k]              + bhh1[k];
            float gv = acc[STAGE_K + r]     + bih1[2 * HIDDEN + k] + bhh1[2 * HIDDEN + k];
            float ov = acc[2 * STAGE_K + r] + bih1[3 * HIDDEN + k] + bhh1[3 * HIDDEN + k];
            float c  = sigm(iv) * tanh_fast(gv);
            float h  = sigm(ov) * tanh_fast(c);
            // heads fused: h1 never materialized
            #pragma unroll
            for (int a = 0; a < NACT + 1; a++) {
                pv[a] = fmaf(hw[a * HIDDEN + k], h, pv[a]);   // broadcast LDS
            }
        }
    }

    // ---- output: policy [B,16] then value [B,1] (flattened concat) ----
    float4* po = reinterpret_cast<float4*>(out + (size_t)row * NACT);
    #pragma unroll
    for (int a4 = 0; a4 < NACT / 4; a4++) {
        float4 v;
        v.x = pv[4 * a4 + 0]; v.y = pv[4 * a4 + 1];
        v.z = pv[4 * a4 + 2]; v.w = pv[4 * a4 + 3];
        po[a4] = v;
    }
    out[(size_t)BATCH * NACT + row] = pv[NACT];
}

extern "C" void kernel_launch(void* const* d_in, const int* in_sizes, int n_in,
                              void* d_out, int out_size) {
    const float* x    = (const float*)d_in[0];
    const float* Wih0 = (const float*)d_in[1];
    // d_in[2] = Whh0 : dead (zero initial hidden state)
    const float* bih0 = (const float*)d_in[3];
    const float* bhh0 = (const float*)d_in[4];
    const float* Wih1 = (const float*)d_in[5];
    // d_in[6] = Whh1 : dead
    const float* bih1 = (const float*)d_in[7];
    const float* bhh1 = (const float*)d_in[8];
    const float* Wp   = (const float*)d_in[9];
    const float* bp   = (const float*)d_in[10];
    const float* Wv   = (const float*)d_in[11];
    const float* bv   = (const float*)d_in[12];
    float* out = (float*)d_out;

    const size_t smem = (size_t)(TPB * HB_STRIDE + STAGE_ROWS * HIDDEN + 17 * HIDDEN) * sizeof(float);
    cudaFuncSetAttribute(lstm_policy_fused,
                         cudaFuncAttributeMaxDynamicSharedMemorySize, (int)smem);

    lstm_policy_fused<<<BATCH / TPB, TPB, smem>>>(
        x, Wih0, bih0, bhh0, Wih1, bih1, bhh1, Wp, bp, Wv, bv, out);
}

// round 4
// speedup vs baseline: 1.0318x; 1.0318x over previous
#include <cuda_runtime.h>

// LSTMPolicy fused, round 2: packed f32x2 FFMA2, h in registers (no hbuf smem),
// tanh.approx MUFU, 3 CTAs/SM.
// Algebra: zero init state => Whh* dead, f-gate dead (c = sigm(i)*tanh(g)).

#define BATCH   65536
#define HIDDEN  128
#define INPUT   64
#define NACT    16
#define TPB     128
#define KCH     8                 // k-values per stage
#define SROWS   (3 * KCH)         // staged gate rows (i,g,o) = 24

typedef unsigned long long u64;

__device__ __forceinline__ void fma2(u64& d, u64 a, u64 b) {
    asm("fma.rn.f32x2 %0, %1, %2, %0;" : "+l"(d) : "l"(a), "l"(b));
}
__device__ __forceinline__ float hsum2(u64 v) {
    float lo, hi;
    asm("mov.b64 {%0, %1}, %2;" : "=f"(lo), "=f"(hi) : "l"(v));
    return lo + hi;
}
__device__ __forceinline__ u64 pack2(float lo, float hi) {
    u64 r;
    asm("mov.b64 %0, {%1, %2};" : "=l"(r) : "f"(lo), "f"(hi));
    return r;
}
__device__ __forceinline__ float tanh_ap(float x) {
    float y;
    asm("tanh.approx.f32 %0, %1;" : "=f"(y) : "f"(x));
    return y;
}
__device__ __forceinline__ float sigm(float x) {
    // sigmoid(x) = 0.5*tanh(0.5x) + 0.5  (single MUFU)
    return fmaf(0.5f, tanh_ap(0.5f * x), 0.5f);
}

__global__ __launch_bounds__(TPB, 3)
void lstm_policy_fused(const float* __restrict__ x,
                       const float* __restrict__ Wih0,
                       const float* __restrict__ bih0,
                       const float* __restrict__ bhh0,
                       const float* __restrict__ Wih1,
                       const float* __restrict__ bih1,
                       const float* __restrict__ bhh1,
                       const float* __restrict__ Wp,
                       const float* __restrict__ bp,
                       const float* __restrict__ Wv,
                       const float* __restrict__ bv,
                       float* __restrict__ out)
{
    __shared__ __align__(16) float wst[SROWS * HIDDEN];     // weight stage (max 24x128)
    __shared__ float bias0[3 * HIDDEN];                     // bih+bhh, gates i,g,o
    __shared__ float bias1[3 * HIDDEN];
    __shared__ __align__(16) float hw[17 * HIDDEN];         // head weights (Wp;Wv)
    __shared__ float hb[17];

    const int t   = threadIdx.x;
    const int row = blockIdx.x * TPB + t;

    // ---- one-time staging: combined biases + head weights ----
    for (int i = t; i < HIDDEN; i += TPB) {
        bias0[i]              = bih0[i]              + bhh0[i];
        bias0[HIDDEN + i]     = bih0[2*HIDDEN + i]   + bhh0[2*HIDDEN + i];
        bias0[2*HIDDEN + i]   = bih0[3*HIDDEN + i]   + bhh0[3*HIDDEN + i];
        bias1[i]              = bih1[i]              + bhh1[i];
        bias1[HIDDEN + i]     = bih1[2*HIDDEN + i]   + bhh1[2*HIDDEN + i];
        bias1[2*HIDDEN + i]   = bih1[3*HIDDEN + i]   + bhh1[3*HIDDEN + i];
    }
    for (int i = t; i < 17 * HIDDEN; i += TPB)
        hw[i] = (i < NACT * HIDDEN) ? Wp[i] : Wv[i - NACT * HIDDEN];
    if (t < NACT)  hb[t] = bp[t];
    if (t == NACT) hb[t] = bv[0];
    // first stage's __syncthreads() below covers these before any consumer

    // ---- x row into packed f32x2 registers ----
    u64 xr[INPUT / 2];
    {
        const ulonglong2* xg = reinterpret_cast<const ulonglong2*>(x + (size_t)row * INPUT);
        #pragma unroll
        for (int j = 0; j < INPUT / 4; j++) {
            ulonglong2 v = __ldg(xg + j);
            xr[2*j] = v.x; xr[2*j + 1] = v.y;
        }
    }

    u64 h2[HIDDEN / 2];   // layer-0 output, packed pairs, thread-private

    // ======================= Layer 0 =======================
    for (int s = 0; s < HIDDEN / KCH; s++) {
        const int k0 = s * KCH;
        __syncthreads();
        // stage 24 gate rows (i,g,o) x 64 cols
        for (int idx = t; idx < SROWS * (INPUT / 4); idx += TPB) {
            int r = idx / (INPUT / 4), c4 = idx % (INPUT / 4);
            int gate = r >> 3, kk = k0 + (r & 7);
            int grow = (gate == 0) ? kk : (gate == 1) ? (2*HIDDEN + kk) : (3*HIDDEN + kk);
            reinterpret_cast<float4*>(wst)[r * (INPUT/4) + c4] =
                reinterpret_cast<const float4*>(Wih0)[grow * (INPUT/4) + c4];
        }
        __syncthreads();

        u64 acc[SROWS];
        #pragma unroll
        for (int r = 0; r < SROWS; r++) acc[r] = 0ull;

        #pragma unroll
        for (int j4 = 0; j4 < INPUT / 4; j4++) {
            const u64 a0 = xr[2*j4], a1 = xr[2*j4 + 1];
            #pragma unroll
            for (int r = 0; r < SROWS; r++) {
                ulonglong2 w = reinterpret_cast<const ulonglong2*>(wst + r * INPUT)[j4];
                fma2(acc[r], w.x, a0);
                fma2(acc[r], w.y, a1);
            }
        }

        #pragma unroll
        for (int r = 0; r < KCH; r += 2) {
            float hv[2];
            #pragma unroll
            for (int u = 0; u < 2; u++) {
                const int k = k0 + r + u;
                float iv = hsum2(acc[r + u])           + bias0[k];
                float gv = hsum2(acc[KCH + r + u])     + bias0[HIDDEN + k];
                float ov = hsum2(acc[2*KCH + r + u])   + bias0[2*HIDDEN + k];
                float c  = sigm(iv) * tanh_ap(gv);
                hv[u]    = sigm(ov) * tanh_ap(c);
            }
            h2[(k0 + r) / 2] = pack2(hv[0], hv[1]);
        }
    }

    // ================= Layer 1 + fused heads =================
    float pv[NACT + 1];
    #pragma unroll
    for (int a = 0; a < NACT + 1; a++) pv[a] = hb[a];

    for (int s = 0; s < HIDDEN / KCH; s++) {
        const int k0 = s * KCH;
        __syncthreads();
        for (int idx = t; idx < SROWS * (HIDDEN / 4); idx += TPB) {
            int r = idx / (HIDDEN / 4), c4 = idx % (HIDDEN / 4);
            int gate = r >> 3, kk = k0 + (r & 7);
            int grow = (gate == 0) ? kk : (gate == 1) ? (2*HIDDEN + kk) : (3*HIDDEN + kk);
            reinterpret_cast<float4*>(wst)[r * (HIDDEN/4) + c4] =
                reinterpret_cast<const float4*>(Wih1)[grow * (HIDDEN/4) + c4];
        }
        __syncthreads();

        u64 acc[SROWS];
        #pragma unroll
        for (int r = 0; r < SROWS; r++) acc[r] = 0ull;

        #pragma unroll
        for (int j4 = 0; j4 < HIDDEN / 4; j4++) {
            const u64 a0 = h2[2*j4], a1 = h2[2*j4 + 1];
            #pragma unroll
            for (int r = 0; r < SROWS; r++) {
                ulonglong2 w = reinterpret_cast<const ulonglong2*>(wst + r * HIDDEN)[j4];
                fma2(acc[r], w.x, a0);
                fma2(acc[r], w.y, a1);
            }
        }

        #pragma unroll
        for (int r = 0; r < KCH; r++) {
            const int k = k0 + r;
            float iv = hsum2(acc[r])          + bias1[k];
            float gv = hsum2(acc[KCH + r])    + bias1[HIDDEN + k];
            float ov = hsum2(acc[2*KCH + r])  + bias1[2*HIDDEN + k];
            float c  = sigm(iv) * tanh_ap(gv);
            float h  = sigm(ov) * tanh_ap(c);
            // heads fused: h1 never materialized (scalar FFMA, ~3% of MACs)
            #pragma unroll
            for (int a = 0; a < NACT + 1; a++)
                pv[a] = fmaf(hw[a * HIDDEN + k], h, pv[a]);
        }
    }

    // ---- output: policy [B,16], value [B,1] appended ----
    float4* po = reinterpret_cast<float4*>(out + (size_t)row * NACT);
    #pragma unroll
    for (int a4 = 0; a4 < NACT / 4; a4++) {
        float4 v;
        v.x = pv[4*a4 + 0]; v.y = pv[4*a4 + 1];
        v.z = pv[4*a4 + 2]; v.w = pv[4*a4 + 3];
        po[a4] = v;
    }
    out[(size_t)BATCH * NACT + row] = pv[NACT];
}

extern "C" void kernel_launch(void* const* d_in, const int* in_sizes, int n_in,
                              void* d_out, int out_size) {
    const float* x    = (const float*)d_in[0];
    const float* Wih0 = (const float*)d_in[1];
    // d_in[2] = Whh0 : dead (zero initial hidden state)
    const float* bih0 = (const float*)d_in[3];
    const float* bhh0 = (const float*)d_in[4];
    const float* Wih1 = (const float*)d_in[5];
    // d_in[6] = Whh1 : dead
    const float* bih1 = (const float*)d_in[7];
    const float* bhh1 = (const float*)d_in[8];
    const float* Wp   = (const float*)d_in[9];
    const float* bp   = (const float*)d_in[10];
    const float* Wv   = (const float*)d_in[11];
    const float* bv   = (const float*)d_in[12];
    float* out = (float*)d_out;

    lstm_policy_fused<<<BATCH / TPB, TPB>>>(
        x, Wih0, bih0, bhh0, Wih1, bih1, bhh1, Wp, bp, Wv, bv, out);
}

// round 9
// speedup vs baseline: 3.5875x; 3.4771x over previous
#include <cuda_runtime.h>
#include <cuda_bf16.h>

// LSTMPolicy via mma.sync.m16n8k16 bf16 hi/lo 3-split (baseline PTX, no sm_103a features).
// Zero init state => Whh* dead, f-gate dead (c = sigm(i)*tanh(g)).
// CTA = 128 batch rows, 256 threads (8 warps x 16 rows), fused L0->L1->heads.
// Weights prebaked into padded smem-layout gmem images; staged via linear cp.async.

#define BATCH   65536
#define NACT    16
#define TPB     256
#define NBLK    512               // 65536 / 128 rows per CTA

#define RS      272               // row stride bytes (128 bf16 data + 8 pad) -> conflict-free ldmatrix
#define CHUNK_B 26112             // LSTM chunk: 48 rows x 272 x 2 (hi+lo)
#define HD_B    17408             // head chunk: 32 rows x 272 x 2
#define OFF_L0  0
#define OFF_L1  208896            // 8 * 26112
#define OFF_HD  417792            // + 8 * 26112
#define WIMG_BYTES 435200

__device__ __align__(16) unsigned char g_wimg[WIMG_BYTES];
__device__ float g_bc0[384];      // [i,g,o] combined bih+bhh
__device__ float g_bc1[384];
__device__ float g_bch[32];       // head bias, zero-padded

// ---- smem byte offsets ----
#define SM_BIAS  0                // 800 floats
#define SA0HI    3200
#define SA0LO    38016
#define SA1HI    72832
#define SA1LO    107648
#define SW0      142464
#define SW1      168576
#define SMEM_TOTAL 194688

static __device__ __forceinline__ unsigned smem_u32(const void* p) {
    unsigned a;
    asm("{ .reg .u64 t; cvta.to.shared.u64 t, %1; cvt.u32.u64 %0, t; }" : "=r"(a) : "l"(p));
    return a;
}
static __device__ __forceinline__ float tanh_ap(float x) {
    float y; asm("tanh.approx.f32 %0, %1;" : "=f"(y) : "f"(x)); return y;
}
static __device__ __forceinline__ float sigm(float x) {
    return fmaf(0.5f, tanh_ap(0.5f * x), 0.5f);
}

#define LDSM4(r, ad) asm volatile( \
    "ldmatrix.sync.aligned.m8n8.x4.shared.b16 {%0,%1,%2,%3}, [%4];" \
    : "=r"((r)[0]),"=r"((r)[1]),"=r"((r)[2]),"=r"((r)[3]) : "r"(ad))

#define MMA(c, a, b0, b1) asm volatile( \
    "mma.sync.aligned.m16n8k16.row.col.f32.bf16.bf16.f32 " \
    "{%0,%1,%2,%3}, {%4,%5,%6,%7}, {%8,%9}, {%0,%1,%2,%3};" \
    : "+f"((c)[0]),"+f"((c)[1]),"+f"((c)[2]),"+f"((c)[3]) \
    : "r"((a)[0]),"r"((a)[1]),"r"((a)[2]),"r"((a)[3]), "r"(b0),"r"(b1))

#define STS32(ad, v) asm volatile("st.shared.b32 [%0], %1;" :: "r"(ad), "r"(v) : "memory")

static __device__ __forceinline__ void stage(unsigned sdst, const unsigned char* gsrc,
                                             int granules, int tid) {
    for (int i = tid; i < granules; i += TPB)
        asm volatile("cp.async.cg.shared.global [%0], [%1], 16;"
                     :: "r"(sdst + i * 16), "l"(gsrc + (size_t)i * 16));
    asm volatile("cp.async.commit_group;" ::: "memory");
}

// 3-pass hi/lo split GEMM over one weight chunk.
// NG groups of 16 n-cols (rows g*16..g*16+15 of chunk image), NK k-steps of 16.
template<int NK, int NG>
static __device__ __forceinline__ void chunk_mma(float (*acc)[2][4],
        unsigned sa_hi, unsigned sa_lo, unsigned sw_hi, unsigned sw_lo,
        unsigned aoff, unsigned boff) {
    #pragma unroll
    for (int p = 0; p < 3; p++) {
        unsigned Ab = (p == 2 ? sa_lo : sa_hi) + aoff;
        unsigned Bb = (p == 1 ? sw_lo : sw_hi) + boff;
        #pragma unroll
        for (int kk = 0; kk < NK; kk++) {
            unsigned a[4];
            LDSM4(a, Ab + kk * 32);
            #pragma unroll
            for (int g = 0; g < NG; g++) {
                unsigned b[4];
                LDSM4(b, Bb + g * (16 * RS) + kk * 32);
                MMA(acc[g][0], a, b[0], b[1]);
                MMA(acc[g][1], a, b[2], b[3]);
            }
        }
    }
}

static __device__ __forceinline__ unsigned pack_bf16(float a, float b) {
    return (unsigned)__bfloat16_as_ushort(__float2bfloat16_rn(a)) |
           ((unsigned)__bfloat16_as_ushort(__float2bfloat16_rn(b)) << 16);
}

// ======================= weight-prep kernel =======================
__global__ void prep_weights(const float* __restrict__ W0, const float* __restrict__ W1,
                             const float* __restrict__ Wp, const float* __restrict__ Wv,
                             const float* __restrict__ bih0, const float* __restrict__ bhh0,
                             const float* __restrict__ bih1, const float* __restrict__ bhh1,
                             const float* __restrict__ bp,  const float* __restrict__ bv) {
    int id = blockIdx.x * 256 + threadIdx.x;
    if (id < 27200) {            // one 16B granule each (8 bf16)
        float w[8];
        #pragma unroll
        for (int j = 0; j < 8; j++) w[j] = 0.0f;
        int split;
        if (id < 13056) {                         // L0: 8 chunks, K=64
            int q = id % 1632; split = q / 816; q %= 816;
            int rr = q / 17, cg = q % 17;
            if (cg < 8) {
                int gate = rr >> 4, kout = (id / 1632) * 16 + (rr & 15);
                int sr = (gate == 0) ? kout : (gate == 1) ? 256 + kout : 384 + kout;
                #pragma unroll
                for (int j = 0; j < 8; j++) w[j] = W0[sr * 64 + cg * 8 + j];
            }
        } else if (id < 26112) {                  // L1: 8 chunks, K=128
            int i = id - 13056;
            int q = i % 1632; split = q / 816; q %= 816;
            int rr = q / 17, cg = q % 17;
            if (cg < 16) {
                int gate = rr >> 4, kout = (i / 1632) * 16 + (rr & 15);
                int sr = (gate == 0) ? kout : (gate == 1) ? 256 + kout : 384 + kout;
                #pragma unroll
                for (int j = 0; j < 8; j++) w[j] = W1[sr * 128 + cg * 8 + j];
            }
        } else {                                  // heads: 32 rows (16 Wp, 1 Wv, 15 zero)
            int q = id - 26112; split = q / 544; q %= 544;
            int rr = q / 17, cg = q % 17;
            if (cg < 16 && rr <= 16) {
                #pragma unroll
                for (int j = 0; j < 8; j++)
                    w[j] = (rr < 16) ? Wp[rr * 128 + cg * 8 + j] : Wv[cg * 8 + j];
            }
        }
        unsigned v[4];
        #pragma unroll
        for (int j = 0; j < 4; j++) {
            float a = w[2 * j], b = w[2 * j + 1];
            if (split) {                          // lo residual
                a -= __bfloat162float(__float2bfloat16_rn(a));
                b -= __bfloat162float(__float2bfloat16_rn(b));
            }
            v[j] = (unsigned)__bfloat16_as_ushort(__float2bfloat16_rn(a)) |
                   ((unsigned)__bfloat16_as_ushort(__float2bfloat16_rn(b)) << 16);
        }
        *reinterpret_cast<uint4*>(g_wimg + (size_t)id * 16) = make_uint4(v[0], v[1], v[2], v[3]);
    } else if (id < 28000) {
        int i = id - 27200;
        if (i < 384) {
            int gate = i / 128, k = i % 128;
            int sr = (gate == 0) ? k : (gate == 1) ? 256 + k : 384 + k;
            g_bc0[i] = bih0[sr] + bhh0[sr];
        } else if (i < 768) {
            int j = i - 384, gate = j / 128, k = j % 128;
            int sr = (gate == 0) ? k : (gate == 1) ? 256 + k : 384 + k;
            g_bc1[j] = bih1[sr] + bhh1[sr];
        } else if (i < 800) {
            int n = i - 768;
            g_bch[n] = (n < NACT) ? bp[n] : (n == NACT) ? bv[0] : 0.0f;
        }
    }
}

// ======================= main fused kernel =======================
__global__ __launch_bounds__(TPB)
void lstm_mma(const float* __restrict__ x, float* __restrict__ out) {
    extern __shared__ __align__(16) char sm[];
    const unsigned sb = smem_u32(sm);
    const int tid  = threadIdx.x;
    const int warp = tid >> 5;
    const int lane = tid & 31;
    float* bias_sm = reinterpret_cast<float*>(sm + SM_BIAS);

    // ---- biases to smem ----
    for (int i = tid; i < 800; i += TPB)
        bias_sm[i] = (i < 384) ? g_bc0[i] : (i < 768) ? g_bc1[i - 384] : g_bch[i - 768];

    // ---- x (128 rows x 64 f32) -> bf16 hi/lo into SA0 ----
    {
        int row = tid >> 1, half = tid & 1;
        const float4* xg = reinterpret_cast<const float4*>(
            x + ((size_t)blockIdx.x * 128 + row) * 64 + half * 32);
        unsigned hp[16], lp[16];
        #pragma unroll
        for (int j = 0; j < 8; j++) {
            float4 v = __ldg(xg + j);
            float e[4] = {v.x, v.y, v.z, v.w};
            #pragma unroll
            for (int q = 0; q < 2; q++) {
                float a = e[2 * q], b = e[2 * q + 1];
                float ah = __bfloat162float(__float2bfloat16_rn(a));
                float bh = __bfloat162float(__float2bfloat16_rn(b));
                hp[2 * j + q] = pack_bf16(a, b);
                lp[2 * j + q] = pack_bf16(a - ah, b - bh);
            }
        }
        unsigned base = row * RS + half * 64;
        *reinterpret_cast<uint4*>(sm + SA0HI + base)      = *reinterpret_cast<uint4*>(hp);
        *reinterpret_cast<uint4*>(sm + SA0HI + base + 16) = *reinterpret_cast<uint4*>(hp + 4);
        *reinterpret_cast<uint4*>(sm + SA0HI + base + 32) = *reinterpret_cast<uint4*>(hp + 8);
        *reinterpret_cast<uint4*>(sm + SA0HI + base + 48) = *reinterpret_cast<uint4*>(hp + 12);
        *reinterpret_cast<uint4*>(sm + SA0LO + base)      = *reinterpret_cast<uint4*>(lp);
        *reinterpret_cast<uint4*>(sm + SA0LO + base + 16) = *reinterpret_cast<uint4*>(lp + 4);
        *reinterpret_cast<uint4*>(sm + SA0LO + base + 32) = *reinterpret_cast<uint4*>(lp + 8);
        *reinterpret_cast<uint4*>(sm + SA0LO + base + 48) = *reinterpret_cast<uint4*>(lp + 12);
    }

    // per-thread ldmatrix address components
    const int mrow = lane & 7, msel = lane >> 3;
    const unsigned aoff = (unsigned)(16 * warp + ((msel & 1) << 3) + mrow) * RS + ((msel >> 1) << 4);
    const unsigned boff = (unsigned)(((msel >> 1) << 3) + mrow) * RS + ((msel & 1) << 4);
    const int t4 = lane >> 2, kp = (lane & 3) * 2;

    stage(sb + SW0, g_wimg + OFF_L0, CHUNK_B / 16, tid);   // prefetch chunk 0

    for (int ci = 0; ci < 17; ci++) {
        if (ci < 16) {
            int nx = ci + 1;
            unsigned dst = (nx & 1) ? sb + SW1 : sb + SW0;
            const unsigned char* src = g_wimg +
                (nx < 8 ? OFF_L0 + nx * CHUNK_B
                        : nx < 16 ? OFF_L1 + (nx - 8) * CHUNK_B : OFF_HD);
            stage(dst, src, (nx == 16 ? HD_B : CHUNK_B) / 16, tid);
            asm volatile("cp.async.wait_group 1;" ::: "memory");
        } else {
            asm volatile("cp.async.wait_group 0;" ::: "memory");
        }
        __syncthreads();

        unsigned swh = (ci & 1) ? sb + SW1 : sb + SW0;
        unsigned swl = swh + (ci == 16 ? HD_B / 2 : CHUNK_B / 2);

        if (ci < 16) {
            const bool l0 = ci < 8;
            const int  c  = l0 ? ci : ci - 8;
            const unsigned sahi = l0 ? sb + SA0HI : sb + SA1HI;
            const unsigned salo = l0 ? sb + SA0LO : sb + SA1LO;
            const unsigned dsth = l0 ? sb + SA1HI : sb + SA0HI;
            const unsigned dstl = l0 ? sb + SA1LO : sb + SA0LO;
            const float* bias = bias_sm + (l0 ? 0 : 384);

            float acc[3][2][4];
            #pragma unroll
            for (int g = 0; g < 3; g++)
                #pragma unroll
                for (int nt = 0; nt < 2; nt++) {
                    float2 bb = *reinterpret_cast<const float2*>(
                        bias + g * 128 + 16 * c + 8 * nt + kp);
                    acc[g][nt][0] = bb.x; acc[g][nt][1] = bb.y;
                    acc[g][nt][2] = bb.x; acc[g][nt][3] = bb.y;
                }

            if (l0) chunk_mma<4, 3>(acc, sahi, salo, swh, swl, aoff, boff);
            else    chunk_mma<8, 3>(acc, sahi, salo, swh, swl, aoff, boff);

            // epilogue: activations -> h bf16 hi/lo into dst A buffer
            #pragma unroll
            for (int rh = 0; rh < 2; rh++) {
                int row = 16 * warp + t4 + 8 * rh;
                #pragma unroll
                for (int nt = 0; nt < 2; nt++) {
                    float hv[2], lv[2];
                    #pragma unroll
                    for (int e = 0; e < 2; e++) {
                        int idx = 2 * rh + e;
                        float cc = sigm(acc[0][nt][idx]) * tanh_ap(acc[1][nt][idx]);
                        float h  = sigm(acc[2][nt][idx]) * tanh_ap(cc);
                        hv[e] = h;
                        lv[e] = h - __bfloat162float(__float2bfloat16_rn(h));
                    }
                    unsigned kb = (unsigned)(16 * c + 8 * nt + kp) * 2;
                    STS32(dsth + row * RS + kb, pack_bf16(hv[0], hv[1]));
                    STS32(dstl + row * RS + kb, pack_bf16(lv[0], lv[1]));
                }
            }
        } else {
            // heads: K=128, 2 n-groups of 16 (cols 0..31; 17 real)
            float acc[2][2][4];
            #pragma unroll
            for (int g = 0; g < 2; g++)
                #pragma unroll
                for (int nt = 0; nt < 2; nt++) {
                    float2 bb = *reinterpret_cast<const float2*>(
                        bias_sm + 768 + g * 16 + 8 * nt + kp);
                    acc[g][nt][0] = bb.x; acc[g][nt][1] = bb.y;
                    acc[g][nt][2] = bb.x; acc[g][nt][3] = bb.y;
                }
            chunk_mma<8, 2>(acc, sb + SA0HI, sb + SA0LO, swh, swl, aoff, boff);

            #pragma unroll
            for (int rh = 0; rh < 2; rh++) {
                size_t r = (size_t)blockIdx.x * 128 + 16 * warp + t4 + 8 * rh;
                #pragma unroll
                for (int nt = 0; nt < 2; nt++) {
                    float2 v = make_float2(acc[0][nt][2 * rh], acc[0][nt][2 * rh + 1]);
                    *reinterpret_cast<float2*>(out + r * NACT + 8 * nt + kp) = v;
                }
                if ((lane & 3) == 0)
                    out[(size_t)BATCH * NACT + r] = acc[1][0][2 * rh];
            }
        }
        __syncthreads();
    }
}

extern "C" void kernel_launch(void* const* d_in, const int* in_sizes, int n_in,
                              void* d_out, int out_size) {
    const float* x    = (const float*)d_in[0];
    const float* Wih0 = (const float*)d_in[1];
    const float* bih0 = (const float*)d_in[3];
    const float* bhh0 = (const float*)d_in[4];
    const float* Wih1 = (const float*)d_in[5];
    const float* bih1 = (const float*)d_in[7];
    const float* bhh1 = (const float*)d_in[8];
    const float* Wp   = (const float*)d_in[9];
    const float* bp   = (const float*)d_in[10];
    const float* Wv   = (const float*)d_in[11];
    const float* bv   = (const float*)d_in[12];
    float* out = (float*)d_out;

    prep_weights<<<110, 256>>>(Wih0, Wih1, Wp, Wv, bih0, bhh0, bih1, bhh1, bp, bv);

    cudaFuncSetAttribute(lstm_mma, cudaFuncAttributeMaxDynamicSharedMemorySize, SMEM_TOTAL);
    lstm_mma<<<NBLK, TPB, SMEM_TOTAL>>>(x, out);
}

// round 11
// speedup vs baseline: 3.7044x; 1.0326x over previous
#include <cuda_runtime.h>
#include <cuda_bf16.h>

// LSTMPolicy via mma.sync m16n8k16 bf16 3-pass hi/lo split.
// R10: M=32 rows/warp (warp = M-pos x N-group), x in registers, 144B L0 rows,
// triple-buffered weight staging with one sync per chunk.
// Zero init state => Whh* dead, f-gate dead (c = sigm(i)*tanh(g)).

#define BATCH   65536
#define NACT    16
#define TPB     256
#define NBLK    512

// weight image (bytes): per chunk [hi half | lo half], rows padded for conflict-free ldsm
#define L0_CHUNK 13824            // 48 rows x 144 x 2
#define L1_CHUNK 26112            // 48 rows x 272 x 2
#define HD_CHUNK 13056            // 24 rows x 272 x 2
#define OFF_L1   110592           // 8 * L0_CHUNK
#define OFF_HD   319488           // OFF_L1 + 8 * L1_CHUNK
#define WIMG_BYTES 332544

__device__ __align__(16) unsigned char g_wimg[WIMG_BYTES];
__device__ float g_bc0[384];      // [i,g,o] combined bih+bhh
__device__ float g_bc1[384];
__device__ float g_bch[32];       // [bp(16), bv, 0...]

// smem byte offsets
#define H0HI 3200
#define H0LO 38016
#define H1HI 72832
#define H1LO 107648
#define SWB  142464               // 3 x 26112 weight buffers
#define SMEM_TOTAL 220800

static __device__ __forceinline__ unsigned smem_u32(const void* p) {
    unsigned a;
    asm("{ .reg .u64 t; cvta.to.shared.u64 t, %1; cvt.u32.u64 %0, t; }" : "=r"(a) : "l"(p));
    return a;
}
static __device__ __forceinline__ float tanh_ap(float x) {
    float y; asm("tanh.approx.f32 %0, %1;" : "=f"(y) : "f"(x)); return y;
}
static __device__ __forceinline__ float sigm(float x) {
    return fmaf(0.5f, tanh_ap(0.5f * x), 0.5f);
}
static __device__ __forceinline__ unsigned pack_bf16(float a, float b) {
    return (unsigned)__bfloat16_as_ushort(__float2bfloat16_rn(a)) |
           ((unsigned)__bfloat16_as_ushort(__float2bfloat16_rn(b)) << 16);
}
static __device__ __forceinline__ float bflo(float a) {
    return a - __bfloat162float(__float2bfloat16_rn(a));
}

#define LDSM4(r, ad) asm volatile( \
    "ldmatrix.sync.aligned.m8n8.x4.shared.b16 {%0,%1,%2,%3}, [%4];" \
    : "=r"((r)[0]),"=r"((r)[1]),"=r"((r)[2]),"=r"((r)[3]) : "r"(ad))
#define LDSM2(r0, r1, ad) asm volatile( \
    "ldmatrix.sync.aligned.m8n8.x2.shared.b16 {%0,%1}, [%2];" \
    : "=r"(r0), "=r"(r1) : "r"(ad))
#define MMA(c, a, b0, b1) asm volatile( \
    "mma.sync.aligned.m16n8k16.row.col.f32.bf16.bf16.f32 " \
    "{%0,%1,%2,%3}, {%4,%5,%6,%7}, {%8,%9}, {%0,%1,%2,%3};" \
    : "+f"((c)[0]),"+f"((c)[1]),"+f"((c)[2]),"+f"((c)[3]) \
    : "r"((a)[0]),"r"((a)[1]),"r"((a)[2]),"r"((a)[3]), "r"(b0),"r"(b1))
#define STS32(ad, v) asm volatile("st.shared.b32 [%0], %1;" :: "r"(ad), "r"(v) : "memory")

static __device__ __forceinline__ void stage(unsigned sdst, const unsigned char* gsrc,
                                             int granules, int tid) {
    for (int i = tid; i < granules; i += TPB)
        asm volatile("cp.async.cg.shared.global [%0], [%1], 16;"
                     :: "r"(sdst + i * 16), "l"(gsrc + (size_t)i * 16));
    asm volatile("cp.async.commit_group;" ::: "memory");
}

// ======================= weight-prep kernel =======================
__global__ void prep_weights(const float* __restrict__ W0, const float* __restrict__ W1,
                             const float* __restrict__ Wp, const float* __restrict__ Wv,
                             const float* __restrict__ bih0, const float* __restrict__ bhh0,
                             const float* __restrict__ bih1, const float* __restrict__ bhh1,
                             const float* __restrict__ bp,  const float* __restrict__ bv) {
    int id = blockIdx.x * 256 + threadIdx.x;
    if (id < 20784) {                 // one 16B granule (8 bf16) of the image
        float w[8];
        #pragma unroll
        for (int j = 0; j < 8; j++) w[j] = 0.0f;
        int half; unsigned addr;
        if (id < 6912) {                                  // L0: 8 chunks, rows 144B
            int c = id / 864, q = id % 864;
            half = q / 432; q %= 432;
            int r = q / 9, gi = q % 9;
            addr = c * L0_CHUNK + half * 6912 + r * 144 + gi * 16;
            if (gi < 8) {
                int gate = r / 16, j = r % 16;
                int sr = (gate == 0) ? 16*c + j : (gate == 1) ? 256 + 16*c + j : 384 + 16*c + j;
                #pragma unroll
                for (int t = 0; t < 8; t++) w[t] = W0[sr * 64 + gi * 8 + t];
            }
        } else if (id < 19968) {                          // L1: 8 chunks, rows 272B
            int i = id - 6912;
            int c = i / 1632, q = i % 1632;
            half = q / 816; q %= 816;
            int r = q / 17, gi = q % 17;
            addr = OFF_L1 + c * L1_CHUNK + half * 13056 + r * 272 + gi * 16;
            if (gi < 16) {
                int gate = r / 16, j = r % 16;
                int sr = (gate == 0) ? 16*c + j : (gate == 1) ? 256 + 16*c + j : 384 + 16*c + j;
                #pragma unroll
                for (int t = 0; t < 8; t++) w[t] = W1[sr * 128 + gi * 8 + t];
            }
        } else {                                          // heads: 24 rows [Wp16, Wv, 0x7]
            int i = id - 19968;
            half = i / 408;
            int q = i % 408, r = q / 17, gi = q % 17;
            addr = OFF_HD + half * 6528 + r * 272 + gi * 16;
            if (gi < 16 && r <= 16) {
                #pragma unroll
                for (int t = 0; t < 8; t++)
                    w[t] = (r < 16) ? Wp[r * 128 + gi * 8 + t] : Wv[gi * 8 + t];
            }
        }
        unsigned v[4];
        #pragma unroll
        for (int j = 0; j < 4; j++) {
            float a = w[2*j], b = w[2*j+1];
            if (half) { a = bflo(a); b = bflo(b); }       // lo residual
            v[j] = pack_bf16(a, b);
        }
        *reinterpret_cast<uint4*>(g_wimg + addr) = make_uint4(v[0], v[1], v[2], v[3]);
    } else if (id < 21584) {
        int i = id - 20784;
        if (i < 384) {
            int gate = i / 128, k = i % 128;
            int sr = (gate == 0) ? k : (gate == 1) ? 256 + k : 384 + k;
            g_bc0[i] = bih0[sr] + bhh0[sr];
        } else if (i < 768) {
            int j = i - 384, gate = j / 128, k = j % 128;
            int sr = (gate == 0) ? k : (gate == 1) ? 256 + k : 384 + k;
            g_bc1[j] = bih1[sr] + bhh1[sr];
        } else {
            int n = i - 768;
            g_bch[n] = (n < NACT) ? bp[n] : (n == NACT) ? bv[0] : 0.0f;
        }
    }
}

// ======================= main fused kernel =======================
__global__ __launch_bounds__(TPB, 1)
void lstm_mma(const float* __restrict__ x, float* __restrict__ out) {
    extern __shared__ __align__(16) char sm[];
    const unsigned sb = smem_u32(sm);
    const int tid  = threadIdx.x;
    const int warp = tid >> 5, lane = tid & 31;
    const int wm = warp & 3, wg = warp >> 2;          // M-position, N-group
    const int mrow = lane & 7, msel = lane >> 3;
    const int t4 = lane >> 2, kp = (lane & 3) * 2;
    float* bias_sm = reinterpret_cast<float*>(sm);

    for (int i = tid; i < 800; i += TPB)
        bias_sm[i] = (i < 384) ? g_bc0[i] : (i < 768) ? g_bc1[i - 384] : g_bch[i - 768];

    stage(sb + SWB, g_wimg, L0_CHUNK / 16, tid);      // prefetch chunk 0

    // ---- x fragments: gmem -> registers (hi/lo), M=32 rows, K=64 ----
    unsigned AH[4][8], AL[4][8];
    {
        const float* xb = x + ((size_t)blockIdx.x * 128 + 32 * wm + t4) * 64;
        #pragma unroll
        for (int rr = 0; rr < 4; rr++) {                      // rows t4 + 8*rr
            const float* xr = xb + rr * 8 * 64;
            #pragma unroll
            for (int kk = 0; kk < 4; kk++) {
                float2 u = __ldg(reinterpret_cast<const float2*>(xr + 16*kk + kp));
                float2 v = __ldg(reinterpret_cast<const float2*>(xr + 16*kk + kp + 8));
                int tile = rr >> 1, sl = rr & 1;
                AH[kk][4*tile + sl]     = pack_bf16(u.x, u.y);
                AH[kk][4*tile + 2 + sl] = pack_bf16(v.x, v.y);
                AL[kk][4*tile + sl]     = pack_bf16(bflo(u.x), bflo(u.y));
                AL[kk][4*tile + 2 + sl] = pack_bf16(bflo(v.x), bflo(v.y));
            }
        }
    }

    // ldmatrix address components
    const unsigned aoff = (unsigned)(32*wm + ((msel & 1) << 3) + mrow) * 272 + ((msel >> 1) << 4);
    const unsigned bsel = (unsigned)((msel & 1) << 4);

    for (int ci = 0; ci < 17; ci++) {
        if (ci < 16) {
            int nx = ci + 1;
            unsigned dst = sb + SWB + (unsigned)(nx % 3) * 26112;
            const unsigned char* src; int gran;
            if (nx < 8)       { src = g_wimg + nx * L0_CHUNK;             gran = L0_CHUNK / 16; }
            else if (nx < 16) { src = g_wimg + OFF_L1 + (nx-8)*L1_CHUNK;  gran = L1_CHUNK / 16; }
            else              { src = g_wimg + OFF_HD;                    gran = HD_CHUNK / 16; }
            stage(dst, src, gran, tid);
            asm volatile("cp.async.wait_group 1;" ::: "memory");
        } else {
            asm volatile("cp.async.wait_group 0;" ::: "memory");
        }
        __syncthreads();                                   // chunk ci visible; prev body done

        const unsigned swb = sb + SWB + (unsigned)(ci % 3) * 26112;

        if (ci < 16) {
            const bool l0 = ci < 8;
            const int  c  = l0 ? ci : ci - 8;
            const int  col0 = 16 * c + 8 * wg + kp;
            const float* bs = bias_sm + (l0 ? 0 : 384);
            const unsigned dsth = sb + (l0 ? H0HI : H1HI);
            const unsigned dstl = sb + (l0 ? H0LO : H1LO);

            float acc[3][2][4];
            #pragma unroll
            for (int g = 0; g < 3; g++) {
                float b0 = bs[g * 128 + col0], b1 = bs[g * 128 + col0 + 1];
                #pragma unroll
                for (int mt = 0; mt < 2; mt++) {
                    acc[g][mt][0] = b0; acc[g][mt][1] = b1;
                    acc[g][mt][2] = b0; acc[g][mt][3] = b1;
                }
            }

            if (l0) {
                // A from registers, K=64, weights rows 144B
                #pragma unroll
                for (int kk = 0; kk < 4; kk++) {
                    #pragma unroll
                    for (int g = 0; g < 3; g++) {
                        unsigned ba = swb + (unsigned)(g*16 + 8*wg + mrow) * 144 + bsel + kk * 32;
                        unsigned bh0, bh1, bl0, bl1;
                        LDSM2(bh0, bh1, ba);
                        LDSM2(bl0, bl1, ba + 6912);
                        MMA(acc[g][0], AH[kk],     bh0, bh1);
                        MMA(acc[g][1], AH[kk] + 4, bh0, bh1);
                        MMA(acc[g][0], AH[kk],     bl0, bl1);
                        MMA(acc[g][1], AH[kk] + 4, bl0, bl1);
                        MMA(acc[g][0], AL[kk],     bh0, bh1);
                        MMA(acc[g][1], AL[kk] + 4, bh0, bh1);
                    }
                }
            } else {
                // A = h0 via ldmatrix, K=128, weights rows 272B
                #pragma unroll
                for (int kk = 0; kk < 8; kk++) {
                    unsigned ah[8], al[8];
                    LDSM4(ah,     sb + H0HI + aoff + kk * 32);
                    LDSM4(ah + 4, sb + H0HI + aoff + 16*272 + kk * 32);
                    LDSM4(al,     sb + H0LO + aoff + kk * 32);
                    LDSM4(al + 4, sb + H0LO + aoff + 16*272 + kk * 32);
                    #pragma unroll
                    for (int g = 0; g < 3; g++) {
                        unsigned ba = swb + (unsigned)(g*16 + 8*wg + mrow) * 272 + bsel + kk * 32;
                        unsigned bh0, bh1, bl0, bl1;
                        LDSM2(bh0, bh1, ba);
                        LDSM2(bl0, bl1, ba + 13056);
                        MMA(acc[g][0], ah,     bh0, bh1);
                        MMA(acc[g][1], ah + 4, bh0, bh1);
                        MMA(acc[g][0], ah,     bl0, bl1);
                        MMA(acc[g][1], ah + 4, bl0, bl1);
                        MMA(acc[g][0], al,     bh0, bh1);
                        MMA(acc[g][1], al + 4, bh0, bh1);
                    }
                }
            }

            // epilogue: activations -> h hi/lo into dst buffers
            #pragma unroll
            for (int mt = 0; mt < 2; mt++)
                #pragma unroll
                for (int e = 0; e < 2; e++) {
                    float i0 = acc[0][mt][2*e], i1 = acc[0][mt][2*e + 1];
                    float g0 = acc[1][mt][2*e], g1 = acc[1][mt][2*e + 1];
                    float o0 = acc[2][mt][2*e], o1 = acc[2][mt][2*e + 1];
                    float c0 = sigm(i0) * tanh_ap(g0), c1 = sigm(i1) * tanh_ap(g1);
                    float h0 = sigm(o0) * tanh_ap(c0), h1 = sigm(o1) * tanh_ap(c1);
                    int row = 32*wm + t4 + 8*e + 16*mt;
                    unsigned off = (unsigned)row * 272 + (unsigned)col0 * 2;
                    STS32(dsth + off, pack_bf16(h0, h1));
                    STS32(dstl + off, pack_bf16(bflo(h0), bflo(h1)));
                }
        } else {
            // heads: A = h1, N-tiles: wg0 -> {rows 0-7, 16-23}, wg1 -> {8-15}
            float acc[2][2][4];
            {
                float p0 = bias_sm[768 + 8*wg + kp], p1 = bias_sm[768 + 8*wg + kp + 1];
                float v0 = bias_sm[768 + 16 + kp],   v1 = bias_sm[768 + 16 + kp + 1];
                #pragma unroll
                for (int mt = 0; mt < 2; mt++) {
                    acc[0][mt][0] = p0; acc[0][mt][1] = p1; acc[0][mt][2] = p0; acc[0][mt][3] = p1;
                    acc[1][mt][0] = v0; acc[1][mt][1] = v1; acc[1][mt][2] = v0; acc[1][mt][3] = v1;
                }
            }
            #pragma unroll
            for (int kk = 0; kk < 8; kk++) {
                unsigned ah[8], al[8];
                LDSM4(ah,     sb + H1HI + aoff + kk * 32);
                LDSM4(ah + 4, sb + H1HI + aoff + 16*272 + kk * 32);
                LDSM4(al,     sb + H1LO + aoff + kk * 32);
                LDSM4(al + 4, sb + H1LO + aoff + 16*272 + kk * 32);

                unsigned ba = swb + (unsigned)(8*wg + mrow) * 272 + bsel + kk * 32;
                unsigned bh0, bh1, bl0, bl1;
                LDSM2(bh0, bh1, ba);
                LDSM2(bl0, bl1, ba + 6528);
                MMA(acc[0][0], ah,     bh0, bh1);
                MMA(acc[0][1], ah + 4, bh0, bh1);
                MMA(acc[0][0], ah,     bl0, bl1);
                MMA(acc[0][1], ah + 4, bl0, bl1);
                MMA(acc[0][0], al,     bh0, bh1);
                MMA(acc[0][1], al + 4, bh0, bh1);

                if (wg == 0) {               // value tile (rows 16-23 of head image)
                    unsigned ba2 = swb + (unsigned)(16 + mrow) * 272 + bsel + kk * 32;
                    LDSM2(bh0, bh1, ba2);
                    LDSM2(bl0, bl1, ba2 + 6528);
                    MMA(acc[1][0], ah,     bh0, bh1);
                    MMA(acc[1][1], ah + 4, bh0, bh1);
                    MMA(acc[1][0], ah,     bl0, bl1);
                    MMA(acc[1][1], ah + 4, bl0, bl1);
                    MMA(acc[1][0], al,     bh0, bh1);
                    MMA(acc[1][1], al + 4, bh0, bh1);
                }
            }
            #pragma unroll
            for (int mt = 0; mt < 2; mt++)
                #pragma unroll
                for (int e = 0; e < 2; e++) {
                    size_t r = (size_t)blockIdx.x * 128 + 32*wm + t4 + 8*e + 16*mt;
                    float2 pv = make_float2(acc[0][mt][2*e], acc[0][mt][2*e + 1]);
                    *reinterpret_cast<float2*>(out + r * NACT + 8*wg + kp) = pv;
                    if (wg == 0 && (lane & 3) == 0)
                        out[(size_t)BATCH * NACT + r] = acc[1][mt][2*e];
                }
        }
    }
}

extern "C" void kernel_launch(void* const* d_in, const int* in_sizes, int n_in,
                              void* d_out, int out_size) {
    const float* x    = (const float*)d_in[0];
    const float* Wih0 = (const float*)d_in[1];
    const float* bih0 = (const float*)d_in[3];
    const float* bhh0 = (const float*)d_in[4];
    const float* Wih1 = (const float*)d_in[5];
    const float* bih1 = (const float*)d_in[7];
    const float* bhh1 = (const float*)d_in[8];
    const float* Wp   = (const float*)d_in[9];
    const float* bp   = (const float*)d_in[10];
    const float* Wv   = (const float*)d_in[11];
    const float* bv   = (const float*)d_in[12];
    float* out = (float*)d_out;

    prep_weights<<<85, 256>>>(Wih0, Wih1, Wp, Wv, bih0, bhh0, bih1, bhh1, bp, bv);

    cudaFuncSetAttribute(lstm_mma, cudaFuncAttributeMaxDynamicSharedMemorySize, SMEM_TOTAL);
    lstm_mma<<<NBLK, TPB, SMEM_TOTAL>>>(x, out);
}

// round 12
// speedup vs baseline: 3.7982x; 1.0253x over previous
#include <cuda_runtime.h>
#include <cuda_bf16.h>

// LSTMPolicy via mma.sync m16n8k16 bf16 3-pass hi/lo split.
// R12: software-pipelined ldmatrix (double-buffered A/B fragments) to hide
// shared-load latency behind MMA issue. Otherwise identical to R10.
// Zero init state => Whh* dead, f-gate dead (c = sigm(i)*tanh(g)).

#define BATCH   65536
#define NACT    16
#define TPB     256
#define NBLK    512

// weight image (bytes): per chunk [hi half | lo half], rows padded for conflict-free ldsm
#define L0_CHUNK 13824            // 48 rows x 144 x 2
#define L1_CHUNK 26112            // 48 rows x 272 x 2
#define HD_CHUNK 13056            // 24 rows x 272 x 2
#define OFF_L1   110592           // 8 * L0_CHUNK
#define OFF_HD   319488           // OFF_L1 + 8 * L1_CHUNK
#define WIMG_BYTES 332544

__device__ __align__(16) unsigned char g_wimg[WIMG_BYTES];
__device__ float g_bc0[384];      // [i,g,o] combined bih+bhh
__device__ float g_bc1[384];
__device__ float g_bch[32];       // [bp(16), bv, 0...]

// smem byte offsets
#define H0HI 3200
#define H0LO 38016
#define H1HI 72832
#define H1LO 107648
#define SWB  142464               // 3 x 26112 weight buffers
#define SMEM_TOTAL 220800

static __device__ __forceinline__ unsigned smem_u32(const void* p) {
    unsigned a;
    asm("{ .reg .u64 t; cvta.to.shared.u64 t, %1; cvt.u32.u64 %0, t; }" : "=r"(a) : "l"(p));
    return a;
}
static __device__ __forceinline__ float tanh_ap(float x) {
    float y; asm("tanh.approx.f32 %0, %1;" : "=f"(y) : "f"(x)); return y;
}
static __device__ __forceinline__ float sigm(float x) {
    return fmaf(0.5f, tanh_ap(0.5f * x), 0.5f);
}
static __device__ __forceinline__ unsigned pack_bf16(float a, float b) {
    return (unsigned)__bfloat16_as_ushort(__float2bfloat16_rn(a)) |
           ((unsigned)__bfloat16_as_ushort(__float2bfloat16_rn(b)) << 16);
}
static __device__ __forceinline__ float bflo(float a) {
    return a - __bfloat162float(__float2bfloat16_rn(a));
}

#define LDSM4(r, ad) asm volatile( \
    "ldmatrix.sync.aligned.m8n8.x4.shared.b16 {%0,%1,%2,%3}, [%4];" \
    : "=r"((r)[0]),"=r"((r)[1]),"=r"((r)[2]),"=r"((r)[3]) : "r"(ad))
#define LDSM2(r0, r1, ad) asm volatile( \
    "ldmatrix.sync.aligned.m8n8.x2.shared.b16 {%0,%1}, [%2];" \
    : "=r"(r0), "=r"(r1) : "r"(ad))
#define MMA(c, a, b0, b1) asm volatile( \
    "mma.sync.aligned.m16n8k16.row.col.f32.bf16.bf16.f32 " \
    "{%0,%1,%2,%3}, {%4,%5,%6,%7}, {%8,%9}, {%0,%1,%2,%3};" \
    : "+f"((c)[0]),"+f"((c)[1]),"+f"((c)[2]),"+f"((c)[3]) \
    : "r"((a)[0]),"r"((a)[1]),"r"((a)[2]),"r"((a)[3]), "r"(b0),"r"(b1))
#define STS32(ad, v) asm volatile("st.shared.b32 [%0], %1;" :: "r"(ad), "r"(v) : "memory")

static __device__ __forceinline__ void stage(unsigned sdst, const unsigned char* gsrc,
                                             int granules, int tid) {
    for (int i = tid; i < granules; i += TPB)
        asm volatile("cp.async.cg.shared.global [%0], [%1], 16;"
                     :: "r"(sdst + i * 16), "l"(gsrc + (size_t)i * 16));
    asm volatile("cp.async.commit_group;" ::: "memory");
}

// ======================= weight-prep kernel =======================
__global__ void prep_weights(const float* __restrict__ W0, const float* __restrict__ W1,
                             const float* __restrict__ Wp, const float* __restrict__ Wv,
                             const float* __restrict__ bih0, const float* __restrict__ bhh0,
                             const float* __restrict__ bih1, const float* __restrict__ bhh1,
                             const float* __restrict__ bp,  const float* __restrict__ bv) {
    int id = blockIdx.x * 256 + threadIdx.x;
    if (id < 20784) {                 // one 16B granule (8 bf16) of the image
        float w[8];
        #pragma unroll
        for (int j = 0; j < 8; j++) w[j] = 0.0f;
        int half; unsigned addr;
        if (id < 6912) {                                  // L0: 8 chunks, rows 144B
            int c = id / 864, q = id % 864;
            half = q / 432; q %= 432;
            int r = q / 9, gi = q % 9;
            addr = c * L0_CHUNK + half * 6912 + r * 144 + gi * 16;
            if (gi < 8) {
                int gate = r / 16, j = r % 16;
                int sr = (gate == 0) ? 16*c + j : (gate == 1) ? 256 + 16*c + j : 384 + 16*c + j;
                #pragma unroll
                for (int t = 0; t < 8; t++) w[t] = W0[sr * 64 + gi * 8 + t];
            }
        } else if (id < 19968) {                          // L1: 8 chunks, rows 272B
            int i = id - 6912;
            int c = i / 1632, q = i % 1632;
            half = q / 816; q %= 816;
            int r = q / 17, gi = q % 17;
            addr = OFF_L1 + c * L1_CHUNK + half * 13056 + r * 272 + gi * 16;
            if (gi < 16) {
                int gate = r / 16, j = r % 16;
                int sr = (gate == 0) ? 16*c + j : (gate == 1) ? 256 + 16*c + j : 384 + 16*c + j;
                #pragma unroll
                for (int t = 0; t < 8; t++) w[t] = W1[sr * 128 + gi * 8 + t];
            }
        } else {                                          // heads: 24 rows [Wp16, Wv, 0x7]
            int i = id - 19968;
            half = i / 408;
            int q = i % 408, r = q / 17, gi = q % 17;
            addr = OFF_HD + half * 6528 + r * 272 + gi * 16;
            if (gi < 16 && r <= 16) {
                #pragma unroll
                for (int t = 0; t < 8; t++)
                    w[t] = (r < 16) ? Wp[r * 128 + gi * 8 + t] : Wv[gi * 8 + t];
            }
        }
        unsigned v[4];
        #pragma unroll
        for (int j = 0; j < 4; j++) {
            float a = w[2*j], b = w[2*j+1];
            if (half) { a = bflo(a); b = bflo(b); }       // lo residual
            v[j] = pack_bf16(a, b);
        }
        *reinterpret_cast<uint4*>(g_wimg + addr) = make_uint4(v[0], v[1], v[2], v[3]);
    } else if (id < 21584) {
        int i = id - 20784;
        if (i < 384) {
            int gate = i / 128, k = i % 128;
            int sr = (gate == 0) ? k : (gate == 1) ? 256 + k : 384 + k;
            g_bc0[i] = bih0[sr] + bhh0[sr];
        } else if (i < 768) {
            int j = i - 384, gate = j / 128, k = j % 128;
            int sr = (gate == 0) ? k : (gate == 1) ? 256 + k : 384 + k;
            g_bc1[j] = bih1[sr] + bhh1[sr];
        } else {
            int n = i - 768;
            g_bch[n] = (n < NACT) ? bp[n] : (n == NACT) ? bv[0] : 0.0f;
        }
    }
}

// ======================= main fused kernel =======================
__global__ __launch_bounds__(TPB, 1)
void lstm_mma(const float* __restrict__ x, float* __restrict__ out) {
    extern __shared__ __align__(16) char sm[];
    const unsigned sb = smem_u32(sm);
    const int tid  = threadIdx.x;
    const int warp = tid >> 5, lane = tid & 31;
    const int wm = warp & 3, wg = warp >> 2;          // M-position, N-group
    const int mrow = lane & 7, msel = lane >> 3;
    const int t4 = lane >> 2, kp = (lane & 3) * 2;
    float* bias_sm = reinterpret_cast<float*>(sm);

    for (int i = tid; i < 800; i += TPB)
        bias_sm[i] = (i < 384) ? g_bc0[i] : (i < 768) ? g_bc1[i - 384] : g_bch[i - 768];

    stage(sb + SWB, g_wimg, L0_CHUNK / 16, tid);      // prefetch chunk 0

    // ---- x fragments: gmem -> registers (hi/lo), M=32 rows, K=64 ----
    unsigned AH[4][8], AL[4][8];
    {
        const float* xb = x + ((size_t)blockIdx.x * 128 + 32 * wm + t4) * 64;
        #pragma unroll
        for (int rr = 0; rr < 4; rr++) {                      // rows t4 + 8*rr
            const float* xr = xb + rr * 8 * 64;
            #pragma unroll
            for (int kk = 0; kk < 4; kk++) {
                float2 u = __ldg(reinterpret_cast<const float2*>(xr + 16*kk + kp));
                float2 v = __ldg(reinterpret_cast<const float2*>(xr + 16*kk + kp + 8));
                int tile = rr >> 1, sl = rr & 1;
                AH[kk][4*tile + sl]     = pack_bf16(u.x, u.y);
                AH[kk][4*tile + 2 + sl] = pack_bf16(v.x, v.y);
                AL[kk][4*tile + sl]     = pack_bf16(bflo(u.x), bflo(u.y));
                AL[kk][4*tile + 2 + sl] = pack_bf16(bflo(v.x), bflo(v.y));
            }
        }
    }

    // ldmatrix address components
    const unsigned aoff = (unsigned)(32*wm + ((msel & 1) << 3) + mrow) * 272 + ((msel >> 1) << 4);
    const unsigned bsel = (unsigned)((msel & 1) << 4);

    for (int ci = 0; ci < 17; ci++) {
        if (ci < 16) {
            int nx = ci + 1;
            unsigned dst = sb + SWB + (unsigned)(nx % 3) * 26112;
            const unsigned char* src; int gran;
            if (nx < 8)       { src = g_wimg + nx * L0_CHUNK;             gran = L0_CHUNK / 16; }
            else if (nx < 16) { src = g_wimg + OFF_L1 + (nx-8)*L1_CHUNK;  gran = L1_CHUNK / 16; }
            else              { src = g_wimg + OFF_HD;                    gran = HD_CHUNK / 16; }
            stage(dst, src, gran, tid);
            asm volatile("cp.async.wait_group 1;" ::: "memory");
        } else {
            asm volatile("cp.async.wait_group 0;" ::: "memory");
        }
        __syncthreads();                                   // chunk ci visible; prev body done

        const unsigned swb = sb + SWB + (unsigned)(ci % 3) * 26112;

        if (ci < 16) {
            const bool l0 = ci < 8;
            const int  c  = l0 ? ci : ci - 8;
            const int  col0 = 16 * c + 8 * wg + kp;
            const float* bs = bias_sm + (l0 ? 0 : 384);
            const unsigned dsth = sb + (l0 ? H0HI : H1HI);
            const unsigned dstl = sb + (l0 ? H0LO : H1LO);

            float acc[3][2][4];
            #pragma unroll
            for (int g = 0; g < 3; g++) {
                float b0 = bs[g * 128 + col0], b1 = bs[g * 128 + col0 + 1];
                #pragma unroll
                for (int mt = 0; mt < 2; mt++) {
                    acc[g][mt][0] = b0; acc[g][mt][1] = b1;
                    acc[g][mt][2] = b0; acc[g][mt][3] = b1;
                }
            }

            if (l0) {
                // A from registers, K=64, weights rows 144B.
                // Software-pipelined B: load kk+1's fragments before kk's MMAs.
                unsigned bh[2][3][2], bl[2][3][2];
                #pragma unroll
                for (int g = 0; g < 3; g++) {
                    unsigned ba = swb + (unsigned)(g*16 + 8*wg + mrow) * 144 + bsel;
                    LDSM2(bh[0][g][0], bh[0][g][1], ba);
                    LDSM2(bl[0][g][0], bl[0][g][1], ba + 6912);
                }
                #pragma unroll
                for (int kk = 0; kk < 4; kk++) {
                    const int cur = kk & 1, nxt = cur ^ 1;
                    if (kk < 3) {
                        #pragma unroll
                        for (int g = 0; g < 3; g++) {
                            unsigned ba = swb + (unsigned)(g*16 + 8*wg + mrow) * 144 + bsel
                                        + (unsigned)(kk + 1) * 32;
                            LDSM2(bh[nxt][g][0], bh[nxt][g][1], ba);
                            LDSM2(bl[nxt][g][0], bl[nxt][g][1], ba + 6912);
                        }
                    }
                    #pragma unroll
                    for (int g = 0; g < 3; g++) {
                        MMA(acc[g][0], AH[kk],     bh[cur][g][0], bh[cur][g][1]);
                        MMA(acc[g][1], AH[kk] + 4, bh[cur][g][0], bh[cur][g][1]);
                        MMA(acc[g][0], AH[kk],     bl[cur][g][0], bl[cur][g][1]);
                        MMA(acc[g][1], AH[kk] + 4, bl[cur][g][0], bl[cur][g][1]);
                        MMA(acc[g][0], AL[kk],     bh[cur][g][0], bh[cur][g][1]);
                        MMA(acc[g][1], AL[kk] + 4, bh[cur][g][0], bh[cur][g][1]);
                    }
                }
            } else {
                // A = h0 via ldmatrix, K=128, rows 272B. Pipelined A and B.
                unsigned ah[2][8], al[2][8], bh[2][3][2], bl[2][3][2];
                LDSM4(ah[0],     sb + H0HI + aoff);
                LDSM4(ah[0] + 4, sb + H0HI + aoff + 16*272);
                LDSM4(al[0],     sb + H0LO + aoff);
                LDSM4(al[0] + 4, sb + H0LO + aoff + 16*272);
                #pragma unroll
                for (int g = 0; g < 3; g++) {
                    unsigned ba = swb + (unsigned)(g*16 + 8*wg + mrow) * 272 + bsel;
                    LDSM2(bh[0][g][0], bh[0][g][1], ba);
                    LDSM2(bl[0][g][0], bl[0][g][1], ba + 13056);
                }
                #pragma unroll
                for (int kk = 0; kk < 8; kk++) {
                    const int cur = kk & 1, nxt = cur ^ 1;
                    if (kk < 7) {
                        const unsigned ko = (unsigned)(kk + 1) * 32;
                        LDSM4(ah[nxt],     sb + H0HI + aoff + ko);
                        LDSM4(ah[nxt] + 4, sb + H0HI + aoff + 16*272 + ko);
                        LDSM4(al[nxt],     sb + H0LO + aoff + ko);
                        LDSM4(al[nxt] + 4, sb + H0LO + aoff + 16*272 + ko);
                        #pragma unroll
                        for (int g = 0; g < 3; g++) {
                            unsigned ba = swb + (unsigned)(g*16 + 8*wg + mrow) * 272 + bsel + ko;
                            LDSM2(bh[nxt][g][0], bh[nxt][g][1], ba);
                            LDSM2(bl[nxt][g][0], bl[nxt][g][1], ba + 13056);
                        }
                    }
                    #pragma unroll
                    for (int g = 0; g < 3; g++) {
                        MMA(acc[g][0], ah[cur],     bh[cur][g][0], bh[cur][g][1]);
                        MMA(acc[g][1], ah[cur] + 4, bh[cur][g][0], bh[cur][g][1]);
                        MMA(acc[g][0], ah[cur],     bl[cur][g][0], bl[cur][g][1]);
                        MMA(acc[g][1], ah[cur] + 4, bl[cur][g][0], bl[cur][g][1]);
                        MMA(acc[g][0], al[cur],     bh[cur][g][0], bh[cur][g][1]);
                        MMA(acc[g][1], al[cur] + 4, bh[cur][g][0], bh[cur][g][1]);
                    }
                }
            }

            // epilogue: activations -> h hi/lo into dst buffers
            #pragma unroll
            for (int mt = 0; mt < 2; mt++)
                #pragma unroll
                for (int e = 0; e < 2; e++) {
                    float i0 = acc[0][mt][2*e], i1 = acc[0][mt][2*e + 1];
                    float g0 = acc[1][mt][2*e], g1 = acc[1][mt][2*e + 1];
                    float o0 = acc[2][mt][2*e], o1 = acc[2][mt][2*e + 1];
                    float c0 = sigm(i0) * tanh_ap(g0), c1 = sigm(i1) * tanh_ap(g1);
                    float h0 = sigm(o0) * tanh_ap(c0), h1 = sigm(o1) * tanh_ap(c1);
                    int row = 32*wm + t4 + 8*e + 16*mt;
                    unsigned off = (unsigned)row * 272 + (unsigned)col0 * 2;
                    STS32(dsth + off, pack_bf16(h0, h1));
                    STS32(dstl + off, pack_bf16(bflo(h0), bflo(h1)));
                }
        } else {
            // heads: A = h1, N-tiles: wg0 -> {rows 0-7, 16-23}, wg1 -> {8-15}
            float acc[2][2][4];
            {
                float p0 = bias_sm[768 + 8*wg + kp], p1 = bias_sm[768 + 8*wg + kp + 1];
                float v0 = bias_sm[768 + 16 + kp],   v1 = bias_sm[768 + 16 + kp + 1];
                #pragma unroll
                for (int mt = 0; mt < 2; mt++) {
                    acc[0][mt][0] = p0; acc[0][mt][1] = p1; acc[0][mt][2] = p0; acc[0][mt][3] = p1;
                    acc[1][mt][0] = v0; acc[1][mt][1] = v1; acc[1][mt][2] = v0; acc[1][mt][3] = v1;
                }
            }
            #pragma unroll
            for (int kk = 0; kk < 8; kk++) {
                unsigned ah[8], al[8];
                LDSM4(ah,     sb + H1HI + aoff + kk * 32);
                LDSM4(ah + 4, sb + H1HI + aoff + 16*272 + kk * 32);
                LDSM4(al,     sb + H1LO + aoff + kk * 32);
                LDSM4(al + 4, sb + H1LO + aoff + 16*272 + kk * 32);

                unsigned ba = swb + (unsigned)(8*wg + mrow) * 272 + bsel + kk * 32;
                unsigned bh0, bh1, bl0, bl1;
                LDSM2(bh0, bh1, ba);
                LDSM2(bl0, bl1, ba + 6528);
                MMA(acc[0][0], ah,     bh0, bh1);
                MMA(acc[0][1], ah + 4, bh0, bh1);
                MMA(acc[0][0], ah,     bl0, bl1);
                MMA(acc[0][1], ah + 4, bl0, bl1);
                MMA(acc[0][0], al,     bh0, bh1);
                MMA(acc[0][1], al + 4, bh0, bh1);

                if (wg == 0) {               // value tile (rows 16-23 of head image)
                    unsigned ba2 = swb + (unsigned)(16 + mrow) * 272 + bsel + kk * 32;
                    LDSM2(bh0, bh1, ba2);
                    LDSM2(bl0, bl1, ba2 + 6528);
                    MMA(acc[1][0], ah,     bh0, bh1);
                    MMA(acc[1][1], ah + 4, bh0, bh1);
                    MMA(acc[1][0], ah,     bl0, bl1);
                    MMA(acc[1][1], ah + 4, bl0, bl1);
                    MMA(acc[1][0], al,     bh0, bh1);
                    MMA(acc[1][1], al + 4, bh0, bh1);
                }
            }
            #pragma unroll
            for (int mt = 0; mt < 2; mt++)
                #pragma unroll
                for (int e = 0; e < 2; e++) {
                    size_t r = (size_t)blockIdx.x * 128 + 32*wm + t4 + 8*e + 16*mt;
                    float2 pv = make_float2(acc[0][mt][2*e], acc[0][mt][2*e + 1]);
                    *reinterpret_cast<float2*>(out + r * NACT + 8*wg + kp) = pv;
                    if (wg == 0 && (lane & 3) == 0)
                        out[(size_t)BATCH * NACT + r] = acc[1][mt][2*e];
                }
        }
    }
}

extern "C" void kernel_launch(void* const* d_in, const int* in_sizes, int n_in,
                              void* d_out, int out_size) {
    const float* x    = (const float*)d_in[0];
    const float* Wih0 = (const float*)d_in[1];
    const float* bih0 = (const float*)d_in[3];
    const float* bhh0 = (const float*)d_in[4];
    const float* Wih1 = (const float*)d_in[5];
    const float* bih1 = (const float*)d_in[7];
    const float* bhh1 = (const float*)d_in[8];
    const float* Wp   = (const float*)d_in[9];
    const float* bp   = (const float*)d_in[10];
    const float* Wv   = (const float*)d_in[11];
    const float* bv   = (const float*)d_in[12];
    float* out = (float*)d_out;

    prep_weights<<<85, 256>>>(Wih0, Wih1, Wp, Wv, bih0, bhh0, bih1, bhh1, bp, bv);

    cudaFuncSetAttribute(lstm_mma, cudaFuncAttributeMaxDynamicSharedMemorySize, SMEM_TOTAL);
    lstm_mma<<<NBLK, TPB, SMEM_TOTAL>>>(x, out);
}

// round 13
// speedup vs baseline: 3.8002x; 1.0005x over previous
#include <cuda_runtime.h>
#include <cuda_bf16.h>

// LSTMPolicy via mma.sync m16n8k16 bf16 3-pass hi/lo split.
// R13: MMA issue reordered into 6 interleaved accumulator chains (gate-major ->
// pass-major) so same-acc spacing (6 instr ~ 48cyc) exceeds HMMA latency (~32cyc).
// Zero init state => Whh* dead, f-gate dead (c = sigm(i)*tanh(g)).

#define BATCH   65536
#define NACT    16
#define TPB     256
#define NBLK    512

#define L0_CHUNK 13824            // 48 rows x 144 x 2
#define L1_CHUNK 26112            // 48 rows x 272 x 2
#define HD_CHUNK 13056            // 24 rows x 272 x 2
#define OFF_L1   110592
#define OFF_HD   319488
#define WIMG_BYTES 332544

__device__ __align__(16) unsigned char g_wimg[WIMG_BYTES];
__device__ float g_bc0[384];
__device__ float g_bc1[384];
__device__ float g_bch[32];

#define H0HI 3200
#define H0LO 38016
#define H1HI 72832
#define H1LO 107648
#define SWB  142464
#define SMEM_TOTAL 220800

static __device__ __forceinline__ unsigned smem_u32(const void* p) {
    unsigned a;
    asm("{ .reg .u64 t; cvta.to.shared.u64 t, %1; cvt.u32.u64 %0, t; }" : "=r"(a) : "l"(p));
    return a;
}
static __device__ __forceinline__ float tanh_ap(float x) {
    float y; asm("tanh.approx.f32 %0, %1;" : "=f"(y) : "f"(x)); return y;
}
static __device__ __forceinline__ float sigm(float x) {
    return fmaf(0.5f, tanh_ap(0.5f * x), 0.5f);
}
static __device__ __forceinline__ unsigned pack_bf16(float a, float b) {
    return (unsigned)__bfloat16_as_ushort(__float2bfloat16_rn(a)) |
           ((unsigned)__bfloat16_as_ushort(__float2bfloat16_rn(b)) << 16);
}
static __device__ __forceinline__ float bflo(float a) {
    return a - __bfloat162float(__float2bfloat16_rn(a));
}

#define LDSM4(r, ad) asm volatile( \
    "ldmatrix.sync.aligned.m8n8.x4.shared.b16 {%0,%1,%2,%3}, [%4];" \
    : "=r"((r)[0]),"=r"((r)[1]),"=r"((r)[2]),"=r"((r)[3]) : "r"(ad))
#define LDSM2(r0, r1, ad) asm volatile( \
    "ldmatrix.sync.aligned.m8n8.x2.shared.b16 {%0,%1}, [%2];" \
    : "=r"(r0), "=r"(r1) : "r"(ad))
#define MMA(c, a, b0, b1) asm volatile( \
    "mma.sync.aligned.m16n8k16.row.col.f32.bf16.bf16.f32 " \
    "{%0,%1,%2,%3}, {%4,%5,%6,%7}, {%8,%9}, {%0,%1,%2,%3};" \
    : "+f"((c)[0]),"+f"((c)[1]),"+f"((c)[2]),"+f"((c)[3]) \
    : "r"((a)[0]),"r"((a)[1]),"r"((a)[2]),"r"((a)[3]), "r"(b0),"r"(b1))
#define STS32(ad, v) asm volatile("st.shared.b32 [%0], %1;" :: "r"(ad), "r"(v) : "memory")

static __device__ __forceinline__ void stage(unsigned sdst, const unsigned char* gsrc,
                                             int granules, int tid) {
    for (int i = tid; i < granules; i += TPB)
        asm volatile("cp.async.cg.shared.global [%0], [%1], 16;"
                     :: "r"(sdst + i * 16), "l"(gsrc + (size_t)i * 16));
    asm volatile("cp.async.commit_group;" ::: "memory");
}

// ======================= weight-prep kernel =======================
__global__ void prep_weights(const float* __restrict__ W0, const float* __restrict__ W1,
                             const float* __restrict__ Wp, const float* __restrict__ Wv,
                             const float* __restrict__ bih0, const float* __restrict__ bhh0,
                             const float* __restrict__ bih1, const float* __restrict__ bhh1,
                             const float* __restrict__ bp,  const float* __restrict__ bv) {
    int id = blockIdx.x * 256 + threadIdx.x;
    if (id < 20784) {
        float w[8];
        #pragma unroll
        for (int j = 0; j < 8; j++) w[j] = 0.0f;
        int half; unsigned addr;
        if (id < 6912) {                                  // L0: 8 chunks, rows 144B
            int c = id / 864, q = id % 864;
            half = q / 432; q %= 432;
            int r = q / 9, gi = q % 9;
            addr = c * L0_CHUNK + half * 6912 + r * 144 + gi * 16;
            if (gi < 8) {
                int gate = r / 16, j = r % 16;
                int sr = (gate == 0) ? 16*c + j : (gate == 1) ? 256 + 16*c + j : 384 + 16*c + j;
                #pragma unroll
                for (int t = 0; t < 8; t++) w[t] = W0[sr * 64 + gi * 8 + t];
            }
        } else if (id < 19968) {                          // L1: 8 chunks, rows 272B
            int i = id - 6912;
            int c = i / 1632, q = i % 1632;
            half = q / 816; q %= 816;
            int r = q / 17, gi = q % 17;
            addr = OFF_L1 + c * L1_CHUNK + half * 13056 + r * 272 + gi * 16;
            if (gi < 16) {
                int gate = r / 16, j = r % 16;
                int sr = (gate == 0) ? 16*c + j : (gate == 1) ? 256 + 16*c + j : 384 + 16*c + j;
                #pragma unroll
                for (int t = 0; t < 8; t++) w[t] = W1[sr * 128 + gi * 8 + t];
            }
        } else {                                          // heads: 24 rows [Wp16, Wv, 0x7]
            int i = id - 19968;
            half = i / 408;
            int q = i % 408, r = q / 17, gi = q % 17;
            addr = OFF_HD + half * 6528 + r * 272 + gi * 16;
            if (gi < 16 && r <= 16) {
                #pragma unroll
                for (int t = 0; t < 8; t++)
                    w[t] = (r < 16) ? Wp[r * 128 + gi * 8 + t] : Wv[gi * 8 + t];
            }
        }
        unsigned v[4];
        #pragma unroll
        for (int j = 0; j < 4; j++) {
            float a = w[2*j], b = w[2*j+1];
            if (half) { a = bflo(a); b = bflo(b); }
            v[j] = pack_bf16(a, b);
        }
        *reinterpret_cast<uint4*>(g_wimg + addr) = make_uint4(v[0], v[1], v[2], v[3]);
    } else if (id < 21584) {
        int i = id - 20784;
        if (i < 384) {
            int gate = i / 128, k = i % 128;
            int sr = (gate == 0) ? k : (gate == 1) ? 256 + k : 384 + k;
            g_bc0[i] = bih0[sr] + bhh0[sr];
        } else if (i < 768) {
            int j = i - 384, gate = j / 128, k = j % 128;
            int sr = (gate == 0) ? k : (gate == 1) ? 256 + k : 384 + k;
            g_bc1[j] = bih1[sr] + bhh1[sr];
        } else {
            int n = i - 768;
            g_bch[n] = (n < NACT) ? bp[n] : (n == NACT) ? bv[0] : 0.0f;
        }
    }
}

// ======================= main fused kernel =======================
__global__ __launch_bounds__(TPB, 1)
void lstm_mma(const float* __restrict__ x, float* __restrict__ out) {
    extern __shared__ __align__(16) char sm[];
    const unsigned sb = smem_u32(sm);
    const int tid  = threadIdx.x;
    const int warp = tid >> 5, lane = tid & 31;
    const int wm = warp & 3, wg = warp >> 2;
    const int mrow = lane & 7, msel = lane >> 3;
    const int t4 = lane >> 2, kp = (lane & 3) * 2;
    float* bias_sm = reinterpret_cast<float*>(sm);

    for (int i = tid; i < 800; i += TPB)
        bias_sm[i] = (i < 384) ? g_bc0[i] : (i < 768) ? g_bc1[i - 384] : g_bch[i - 768];

    stage(sb + SWB, g_wimg, L0_CHUNK / 16, tid);

    // ---- x fragments: gmem -> registers (hi/lo), M=32 rows, K=64 ----
    unsigned AH[4][8], AL[4][8];
    {
        const float* xb = x + ((size_t)blockIdx.x * 128 + 32 * wm + t4) * 64;
        #pragma unroll
        for (int rr = 0; rr < 4; rr++) {
            const float* xr = xb + rr * 8 * 64;
            #pragma unroll
            for (int kk = 0; kk < 4; kk++) {
                float2 u = __ldg(reinterpret_cast<const float2*>(xr + 16*kk + kp));
                float2 v = __ldg(reinterpret_cast<const float2*>(xr + 16*kk + kp + 8));
                int tile = rr >> 1, sl = rr & 1;
                AH[kk][4*tile + sl]     = pack_bf16(u.x, u.y);
                AH[kk][4*tile + 2 + sl] = pack_bf16(v.x, v.y);
                AL[kk][4*tile + sl]     = pack_bf16(bflo(u.x), bflo(u.y));
                AL[kk][4*tile + 2 + sl] = pack_bf16(bflo(v.x), bflo(v.y));
            }
        }
    }

    const unsigned aoff = (unsigned)(32*wm + ((msel & 1) << 3) + mrow) * 272 + ((msel >> 1) << 4);
    const unsigned bsel = (unsigned)((msel & 1) << 4);

    for (int ci = 0; ci < 17; ci++) {
        if (ci < 16) {
            int nx = ci + 1;
            unsigned dst = sb + SWB + (unsigned)(nx % 3) * 26112;
            const unsigned char* src; int gran;
            if (nx < 8)       { src = g_wimg + nx * L0_CHUNK;             gran = L0_CHUNK / 16; }
            else if (nx < 16) { src = g_wimg + OFF_L1 + (nx-8)*L1_CHUNK;  gran = L1_CHUNK / 16; }
            else              { src = g_wimg + OFF_HD;                    gran = HD_CHUNK / 16; }
            stage(dst, src, gran, tid);
            asm volatile("cp.async.wait_group 1;" ::: "memory");
        } else {
            asm volatile("cp.async.wait_group 0;" ::: "memory");
        }
        __syncthreads();

        const unsigned swb = sb + SWB + (unsigned)(ci % 3) * 26112;

        if (ci < 16) {
            const bool l0 = ci < 8;
            const int  c  = l0 ? ci : ci - 8;
            const int  col0 = 16 * c + 8 * wg + kp;
            const float* bs = bias_sm + (l0 ? 0 : 384);
            const unsigned dsth = sb + (l0 ? H0HI : H1HI);
            const unsigned dstl = sb + (l0 ? H0LO : H1LO);

            float acc[3][2][4];
            #pragma unroll
            for (int g = 0; g < 3; g++) {
                float b0 = bs[g * 128 + col0], b1 = bs[g * 128 + col0 + 1];
                #pragma unroll
                for (int mt = 0; mt < 2; mt++) {
                    acc[g][mt][0] = b0; acc[g][mt][1] = b1;
                    acc[g][mt][2] = b0; acc[g][mt][3] = b1;
                }
            }

            if (l0) {
                // A in registers, K=64. Pass-major order: 6 independent acc chains.
                unsigned bh[3][2], bl[3][2];
                #pragma unroll
                for (int kk = 0; kk < 4; kk++) {
                    #pragma unroll
                    for (int g = 0; g < 3; g++) {
                        unsigned ba = swb + (unsigned)(g*16 + 8*wg + mrow) * 144 + bsel + kk * 32;
                        LDSM2(bh[g][0], bh[g][1], ba);
                        LDSM2(bl[g][0], bl[g][1], ba + 6912);
                    }
                    #pragma unroll
                    for (int g = 0; g < 3; g++) {           // pass 1: AH x Bhi
                        MMA(acc[g][0], AH[kk],     bh[g][0], bh[g][1]);
                        MMA(acc[g][1], AH[kk] + 4, bh[g][0], bh[g][1]);
                    }
                    #pragma unroll
                    for (int g = 0; g < 3; g++) {           // pass 2: AH x Blo
                        MMA(acc[g][0], AH[kk],     bl[g][0], bl[g][1]);
                        MMA(acc[g][1], AH[kk] + 4, bl[g][0], bl[g][1]);
                    }
                    #pragma unroll
                    for (int g = 0; g < 3; g++) {           // pass 3: AL x Bhi
                        MMA(acc[g][0], AL[kk],     bh[g][0], bh[g][1]);
                        MMA(acc[g][1], AL[kk] + 4, bh[g][0], bh[g][1]);
                    }
                }
            } else {
                // A = h0 via ldmatrix, K=128. Same pass-major interleave.
                #pragma unroll
                for (int kk = 0; kk < 8; kk++) {
                    unsigned ah[8], al[8], bh[3][2], bl[3][2];
                    const unsigned ko = (unsigned)kk * 32;
                    LDSM4(ah,     sb + H0HI + aoff + ko);
                    LDSM4(ah + 4, sb + H0HI + aoff + 16*272 + ko);
                    LDSM4(al,     sb + H0LO + aoff + ko);
                    LDSM4(al + 4, sb + H0LO + aoff + 16*272 + ko);
                    #pragma unroll
                    for (int g = 0; g < 3; g++) {
                        unsigned ba = swb + (unsigned)(g*16 + 8*wg + mrow) * 272 + bsel + ko;
                        LDSM2(bh[g][0], bh[g][1], ba);
                        LDSM2(bl[g][0], bl[g][1], ba + 13056);
                    }
                    #pragma unroll
                    for (int g = 0; g < 3; g++) {
                        MMA(acc[g][0], ah,     bh[g][0], bh[g][1]);
                        MMA(acc[g][1], ah + 4, bh[g][0], bh[g][1]);
                    }
                    #pragma unroll
                    for (int g = 0; g < 3; g++) {
                        MMA(acc[g][0], ah,     bl[g][0], bl[g][1]);
                        MMA(acc[g][1], ah + 4, bl[g][0], bl[g][1]);
                    }
                    #pragma unroll
                    for (int g = 0; g < 3; g++) {
                        MMA(acc[g][0], al,     bh[g][0], bh[g][1]);
                        MMA(acc[g][1], al + 4, bh[g][0], bh[g][1]);
                    }
                }
            }

            // epilogue: activations -> h hi/lo into dst buffers
            #pragma unroll
            for (int mt = 0; mt < 2; mt++)
                #pragma unroll
                for (int e = 0; e < 2; e++) {
                    float i0 = acc[0][mt][2*e], i1 = acc[0][mt][2*e + 1];
                    float g0 = acc[1][mt][2*e], g1 = acc[1][mt][2*e + 1];
                    float o0 = acc[2][mt][2*e], o1 = acc[2][mt][2*e + 1];
                    float c0 = sigm(i0) * tanh_ap(g0), c1 = sigm(i1) * tanh_ap(g1);
                    float h0 = sigm(o0) * tanh_ap(c0), h1 = sigm(o1) * tanh_ap(c1);
                    int row = 32*wm + t4 + 8*e + 16*mt;
                    unsigned off = (unsigned)row * 272 + (unsigned)col0 * 2;
                    STS32(dsth + off, pack_bf16(h0, h1));
                    STS32(dstl + off, pack_bf16(bflo(h0), bflo(h1)));
                }
        } else {
            // heads: A = h1. wg0 -> policy rows 0-7 + value rows 16-23; wg1 -> rows 8-15.
            float acc[2][2][4];
            {
                float p0 = bias_sm[768 + 8*wg + kp], p1 = bias_sm[768 + 8*wg + kp + 1];
                float v0 = bias_sm[768 + 16 + kp],   v1 = bias_sm[768 + 16 + kp + 1];
                #pragma unroll
                for (int mt = 0; mt < 2; mt++) {
                    acc[0][mt][0] = p0; acc[0][mt][1] = p1; acc[0][mt][2] = p0; acc[0][mt][3] = p1;
                    acc[1][mt][0] = v0; acc[1][mt][1] = v1; acc[1][mt][2] = v0; acc[1][mt][3] = v1;
                }
            }
            #pragma unroll
            for (int kk = 0; kk < 8; kk++) {
                unsigned ah[8], al[8];
                const unsigned ko = (unsigned)kk * 32;
                LDSM4(ah,     sb + H1HI + aoff + ko);
                LDSM4(ah + 4, sb + H1HI + aoff + 16*272 + ko);
                LDSM4(al,     sb + H1LO + aoff + ko);
                LDSM4(al + 4, sb + H1LO + aoff + 16*272 + ko);

                unsigned bh0, bh1, bl0, bl1, ch0, ch1, cl0, cl1;
                unsigned ba = swb + (unsigned)(8*wg + mrow) * 272 + bsel + ko;
                LDSM2(bh0, bh1, ba);
                LDSM2(bl0, bl1, ba + 6528);
                if (wg == 0) {
                    unsigned ba2 = swb + (unsigned)(16 + mrow) * 272 + bsel + ko;
                    LDSM2(ch0, ch1, ba2);
                    LDSM2(cl0, cl1, ba2 + 6528);
                }
                // pass-major, 4 chains when wg==0
                MMA(acc[0][0], ah,     bh0, bh1);
                MMA(acc[0][1], ah + 4, bh0, bh1);
                if (wg == 0) { MMA(acc[1][0], ah,     ch0, ch1);
                               MMA(acc[1][1], ah + 4, ch0, ch1); }
                MMA(acc[0][0], ah,     bl0, bl1);
                MMA(acc[0][1], ah + 4, bl0, bl1);
                if (wg == 0) { MMA(acc[1][0], ah,     cl0, cl1);
                               MMA(acc[1][1], ah + 4, cl0, cl1); }
                MMA(acc[0][0], al,     bh0, bh1);
                MMA(acc[0][1], al + 4, bh0, bh1);
                if (wg == 0) { MMA(acc[1][0], al,     ch0, ch1);
                               MMA(acc[1][1], al + 4, ch0, ch1); }
            }
            #pragma unroll
            for (int mt = 0; mt < 2; mt++)
                #pragma unroll
                for (int e = 0; e < 2; e++) {
                    size_t r = (size_t)blockIdx.x * 128 + 32*wm + t4 + 8*e + 16*mt;
                    float2 pv = make_float2(acc[0][mt][2*e], acc[0][mt][2*e + 1]);
                    *reinterpret_cast<float2*>(out + r * NACT + 8*wg + kp) = pv;
                    if (wg == 0 && (lane & 3) == 0)
                        out[(size_t)BATCH * NACT + r] = acc[1][mt][2*e];
                }
        }
    }
}

extern "C" void kernel_launch(void* const* d_in, const int* in_sizes, int n_in,
                              void* d_out, int out_size) {
    const float* x    = (const float*)d_in[0];
    const float* Wih0 = (const float*)d_in[1];
    const float* bih0 = (const float*)d_in[3];
    const float* bhh0 = (const float*)d_in[4];
    const float* Wih1 = (const float*)d_in[5];
    const float* bih1 = (const float*)d_in[7];
    const float* bhh1 = (const float*)d_in[8];
    const float* Wp   = (const float*)d_in[9];
    const float* bp   = (const float*)d_in[10];
    const float* Wv   = (const float*)d_in[11];
    const float* bv   = (const float*)d_in[12];
    float* out = (float*)d_out;

    prep_weights<<<85, 256>>>(Wih0, Wih1, Wp, Wv, bih0, bhh0, bih1, bhh1, bp, bv);

    cudaFuncSetAttribute(lstm_mma, cudaFuncAttributeMaxDynamicSharedMemorySize, SMEM_TOTAL);
    lstm_mma<<<NBLK, TPB, SMEM_TOTAL>>>(x, out);
}